// round 1
// baseline (speedup 1.0000x reference)
#include <cuda_runtime.h>

#define M_TOTAL 8192
#define KDIM    128
#define INVT    5.0f       // 1 / TEMPERATURE
#define LAMDA_C 1.0f

// Scratch (device globals: no allocation allowed)
__device__ float    dG[M_TOTAL];    // d_i = |f_i|^2 / T
__device__ float    accG[M_TOTAL];  // signed exp sums (base d_i)
__device__ unsigned mG[M_TOTAL];    // encoded row max of similarity
__device__ int      labG[M_TOTAL];  // labels as int32

// ---- helpers --------------------------------------------------------------

__device__ __forceinline__ unsigned long long pk2(float x, float y) {
    unsigned long long r;
    asm("mov.b64 %0, {%1,%2};" : "=l"(r) : "f"(x), "f"(y));
    return r;
}
__device__ __forceinline__ void unpk2(unsigned long long v, float& x, float& y) {
    asm("mov.b64 {%0,%1}, %2;" : "=f"(x), "=f"(y) : "l"(v));
}
__device__ __forceinline__ unsigned long long fma2(unsigned long long a,
                                                   unsigned long long b,
                                                   unsigned long long c) {
    unsigned long long d;
    asm("fma.rn.f32x2 %0, %1, %2, %3;" : "=l"(d) : "l"(a), "l"(b), "l"(c));
    return d;
}
// order-preserving float -> unsigned encoding (for atomicMax)
__device__ __forceinline__ unsigned fenc(float f) {
    unsigned u = __float_as_uint(f);
    return (u >> 31) ? ~u : (u | 0x80000000u);
}
__device__ __forceinline__ float fdec(unsigned e) {
    return (e >> 31) ? __uint_as_float(e & 0x7fffffffu) : __uint_as_float(~e);
}

// ---- kernel 1: per-row norms, label cast, init ---------------------------

__global__ void prep_kernel(const float* __restrict__ feat,
                            const long long* __restrict__ labels) {
    int warp = threadIdx.x >> 5, lane = threadIdx.x & 31;
    int row = blockIdx.x * 8 + warp;
    const float4 v = *reinterpret_cast<const float4*>(feat + row * KDIM + lane * 4);
    float ss = v.x * v.x + v.y * v.y + v.z * v.z + v.w * v.w;
    #pragma unroll
    for (int o = 16; o; o >>= 1) ss += __shfl_xor_sync(0xffffffffu, ss, o);
    if (lane == 0) {
        dG[row]   = ss * INVT;
        accG[row] = 0.0f;
        mG[row]   = 0u;
        labG[row] = (int)labels[row];
    }
}

// ---- kernel 2: fused GEMM + masked exp sums ------------------------------
// Grid (128, 2): blockIdx.x = 64-row tile, blockIdx.y = column half.
// 256 threads, 4x4 micro-tile -> 64x64 output tile per iteration.

__global__ __launch_bounds__(256, 2)
void main_kernel(const float* __restrict__ feat) {
    extern __shared__ float sm[];
    float* As = sm;               // [K=128][64], k-major
    float* Bs = sm + 128 * 64;    // [K=128][64], k-major
    int*   labB = (int*)(sm + 2 * 128 * 64);

    const int t  = threadIdx.x;
    const int tx = t & 15;        // column group
    const int ty = t >> 4;        // row group
    const int rowbase  = blockIdx.x * 64;
    const int colstart = blockIdx.y * 4096;

    // Load A tile (resident for whole block): 64 rows x 128 K
    {
        int m = t & 63, kc = (t >> 6) << 5;
        const float4* src = reinterpret_cast<const float4*>(feat + (rowbase + m) * KDIM + kc);
        #pragma unroll
        for (int j = 0; j < 8; j++) {
            float4 v = src[j];
            int k = kc + 4 * j;
            As[k * 64 + m]       = v.x;
            As[(k + 1) * 64 + m] = v.y;
            As[(k + 2) * 64 + m] = v.z;
            As[(k + 3) * 64 + m] = v.w;
        }
    }

    // Per-thread row constants
    float rD[4]; int rL[4];
    #pragma unroll
    for (int i = 0; i < 4; i++) {
        int gi = rowbase + ty * 4 + i;
        rD[i] = dG[gi];
        rL[i] = labG[gi];
    }

    float acc[4] = {0.f, 0.f, 0.f, 0.f};
    float mx[4]  = {-1e30f, -1e30f, -1e30f, -1e30f};

    for (int ct = 0; ct < 64; ct++) {
        int colbase = colstart + ct * 64;
        __syncthreads();   // protect Bs from previous iteration's readers
        // Load B tile: 64 cols x 128 K (conflict-free transposed store)
        {
            int n = t & 63, kc = (t >> 6) << 5;
            const float4* src = reinterpret_cast<const float4*>(feat + (colbase + n) * KDIM + kc);
            #pragma unroll
            for (int j = 0; j < 8; j++) {
                float4 v = src[j];
                int k = kc + 4 * j;
                Bs[k * 64 + n]       = v.x;
                Bs[(k + 1) * 64 + n] = v.y;
                Bs[(k + 2) * 64 + n] = v.z;
                Bs[(k + 3) * 64 + n] = v.w;
            }
            if (t < 64) labB[t] = labG[colbase + t];
        }
        __syncthreads();

        // 4x4 dot products over K=128 with packed f32x2 FMA
        unsigned long long cc[4][2];
        #pragma unroll
        for (int i = 0; i < 4; i++) { cc[i][0] = 0ull; cc[i][1] = 0ull; }

        #pragma unroll 8
        for (int k = 0; k < KDIM; k++) {
            const float4 a = *reinterpret_cast<const float4*>(&As[k * 64 + ty * 4]);
            const float4 b = *reinterpret_cast<const float4*>(&Bs[k * 64 + tx * 4]);
            unsigned long long b01 = pk2(b.x, b.y), b23 = pk2(b.z, b.w);
            unsigned long long a0 = pk2(a.x, a.x);
            unsigned long long a1 = pk2(a.y, a.y);
            unsigned long long a2 = pk2(a.z, a.z);
            unsigned long long a3 = pk2(a.w, a.w);
            cc[0][0] = fma2(a0, b01, cc[0][0]); cc[0][1] = fma2(a0, b23, cc[0][1]);
            cc[1][0] = fma2(a1, b01, cc[1][0]); cc[1][1] = fma2(a1, b23, cc[1][1]);
            cc[2][0] = fma2(a2, b01, cc[2][0]); cc[2][1] = fma2(a2, b23, cc[2][1]);
            cc[3][0] = fma2(a3, b01, cc[3][0]); cc[3][1] = fma2(a3, b23, cc[3][1]);
        }

        // Epilogue: masked exp accumulation + running max
        #pragma unroll
        for (int i = 0; i < 4; i++) {
            float sv[4];
            unpk2(cc[i][0], sv[0], sv[1]);
            unpk2(cc[i][1], sv[2], sv[3]);
            int gi = rowbase + ty * 4 + i;
            #pragma unroll
            for (int j = 0; j < 4; j++) {
                float sim = sv[j] * INVT;
                mx[i] = fmaxf(mx[i], sim);                 // max includes diagonal
                float e = __expf(sim - rD[i]);
                int gj = colbase + tx * 4 + j;
                float sgn = (rL[i] == labB[tx * 4 + j]) ? LAMDA_C : -1.0f;
                if (gj != gi) acc[i] += sgn * e;           // diagonal excluded from sums
            }
        }
    }

    // Reduce per row across the 16 tx lanes (stays within half-warp: xor bits 0..3)
    #pragma unroll
    for (int i = 0; i < 4; i++) {
        float a = acc[i], m = mx[i];
        #pragma unroll
        for (int o = 8; o; o >>= 1) {
            a += __shfl_xor_sync(0xffffffffu, a, o);
            m = fmaxf(m, __shfl_xor_sync(0xffffffffu, m, o));
        }
        if (tx == 0) {
            int gi = rowbase + ty * 4 + i;
            atomicAdd(&accG[gi], a);
            atomicMax(&mG[gi], fenc(m));
        }
    }
}

// ---- kernel 3: exact max correction + mean -------------------------------

__global__ void final_kernel(float* __restrict__ out) {
    __shared__ double red[1024];
    int t = threadIdx.x;
    double s = 0.0;
    #pragma unroll
    for (int i = 0; i < 8; i++) {
        int r = t + i * 1024;
        float m = fdec(mG[r]);
        // log_prob_r = accG[r] * exp(d_r - max_r)  (exact rebase from d to true max)
        s += (double)(accG[r] * __expf(dG[r] - m));
    }
    red[t] = s;
    __syncthreads();
    for (int o = 512; o; o >>= 1) {
        if (t < o) red[t] += red[t + o];
        __syncthreads();
    }
    if (t == 0) out[0] = (float)(-red[0] / (double)M_TOTAL);
}

// ---- launch --------------------------------------------------------------

extern "C" void kernel_launch(void* const* d_in, const int* in_sizes, int n_in,
                              void* d_out, int out_size) {
    const float*     feat   = (const float*)d_in[0];
    const long long* labels = (const long long*)d_in[1];
    float* out = (float*)d_out;

    cudaFuncSetAttribute(main_kernel, cudaFuncAttributeMaxDynamicSharedMemorySize, 66048);

    prep_kernel<<<M_TOTAL / 8, 256>>>(feat, labels);
    main_kernel<<<dim3(128, 2), 256, 66048>>>(feat);
    final_kernel<<<1, 1024>>>(out);
}

// round 3
// speedup vs baseline: 7.4392x; 7.4392x over previous
#include <cuda_runtime.h>
#include <cuda_bf16.h>
#include <cstdint>

#define M_TOTAL 8192
#define KDIM    128
#define INVT    5.0f

// ---- device globals (no allocation allowed) -------------------------------
__device__ __align__(16) __nv_bfloat16 hiG[M_TOTAL * KDIM];
__device__ float    dG[M_TOTAL];
__device__ float    accG[M_TOTAL];
__device__ unsigned mG[M_TOTAL];
__device__ int      labG[M_TOTAL];

// ---- helpers --------------------------------------------------------------
__device__ __forceinline__ uint32_t smem_to_u32(const void* p) {
    uint32_t a;
    asm("{ .reg .u64 t; cvta.to.shared.u64 t, %1; cvt.u32.u64 %0, t; }" : "=r"(a) : "l"(p));
    return a;
}
__device__ __forceinline__ void cpa16(uint32_t dst, const void* src) {
    asm volatile("cp.async.cg.shared.global [%0], [%1], 16;" :: "r"(dst), "l"(src) : "memory");
}
__device__ __forceinline__ void ldsm4(uint32_t* r, uint32_t addr) {
    asm volatile("ldmatrix.sync.aligned.m8n8.x4.shared.b16 {%0,%1,%2,%3}, [%4];"
                 : "=r"(r[0]), "=r"(r[1]), "=r"(r[2]), "=r"(r[3]) : "r"(addr));
}
__device__ __forceinline__ void mma16816(float* c, const uint32_t* a, uint32_t b0, uint32_t b1) {
    asm volatile("mma.sync.aligned.m16n8k16.row.col.f32.bf16.bf16.f32 "
                 "{%0,%1,%2,%3}, {%4,%5,%6,%7}, {%8,%9}, {%0,%1,%2,%3};"
                 : "+f"(c[0]), "+f"(c[1]), "+f"(c[2]), "+f"(c[3])
                 : "r"(a[0]), "r"(a[1]), "r"(a[2]), "r"(a[3]), "r"(b0), "r"(b1));
}
// order-preserving float <-> unsigned (for atomicMax)
__device__ __forceinline__ unsigned fenc(float f) {
    unsigned u = __float_as_uint(f);
    return (u >> 31) ? ~u : (u | 0x80000000u);
}
__device__ __forceinline__ float fdec(unsigned e) {
    return (e >> 31) ? __uint_as_float(e & 0x7fffffffu) : __uint_as_float(~e);
}

// ---- kernel 1: bf16 cast, per-row norms (fp32, exact), init --------------
__global__ void prep_kernel(const float* __restrict__ feat,
                            const long long* __restrict__ labels) {
    int warp = threadIdx.x >> 5, lane = threadIdx.x & 31;
    int row = blockIdx.x * 8 + warp;
    int base = row * KDIM + lane * 4;
    const float4 v = *reinterpret_cast<const float4*>(feat + base);
    float x[4] = {v.x, v.y, v.z, v.w};
    float ss = 0.f;
    #pragma unroll
    for (int j = 0; j < 4; j++) {
        hiG[base + j] = __float2bfloat16_rn(x[j]);
        ss += x[j] * x[j];
    }
    #pragma unroll
    for (int o = 16; o; o >>= 1) ss += __shfl_xor_sync(0xffffffffu, ss, o);
    if (lane == 0) {
        dG[row]   = ss * INVT;
        accG[row] = 0.0f;
        mG[row]   = 0u;
        labG[row] = (int)labels[row];
    }
}

// ---- kernel 2: bf16 HMMA GEMM (K=128 fully smem-resident) + epilogue -----
// 128x128 tile per CTA, grid (64 col, 64 row), 8 warps in 4x2, 32x64 each.

#define SMEM_A   0
#define SMEM_B   32768
#define SMEM_LAB 65536
#define SMEM_SZ  66048

__global__ void __launch_bounds__(256, 2)
main_kernel() {
    extern __shared__ char smem[];
    const uint32_t sb = smem_to_u32(smem);
    const int t = threadIdx.x;
    const int lane = t & 31, wid = t >> 5;
    const int rowbase = blockIdx.y * 128;
    const int colbase = blockIdx.x * 128;

    // ---- load A (rows) and B (cols) tiles, 128x128 bf16 each, swizzled ----
    {
        const int q = t & 15, r0 = t >> 4;   // quad (16B) within 256B row, base row
        const __nv_bfloat16* Ag = hiG + (size_t)(rowbase + r0) * KDIM + q * 8;
        const __nv_bfloat16* Bg = hiG + (size_t)(colbase + r0) * KDIM + q * 8;
        #pragma unroll
        for (int j = 0; j < 8; j++) {
            int row = r0 + j * 16;
            uint32_t sw = (uint32_t)((q ^ (row & 7)) * 16);
            cpa16(sb + SMEM_A + row * 256 + sw, Ag + (size_t)j * 16 * KDIM);
            cpa16(sb + SMEM_B + row * 256 + sw, Bg + (size_t)j * 16 * KDIM);
        }
    }
    if (t < 128) reinterpret_cast<int*>(smem + SMEM_LAB)[t] = labG[colbase + t];
    asm volatile("cp.async.commit_group;" ::: "memory");
    asm volatile("cp.async.wait_group 0;" ::: "memory");
    __syncthreads();

    // ---- GEMM: warp (wm, wn) computes rows wm*32..+31, cols wn*64..+63 ----
    const int wm = wid & 3, wn = wid >> 2;
    float acc[2][8][4];
    #pragma unroll
    for (int mi = 0; mi < 2; mi++)
        #pragma unroll
        for (int bi = 0; bi < 8; bi++)
            #pragma unroll
            for (int rg = 0; rg < 4; rg++) acc[mi][bi][rg] = 0.f;

    #pragma unroll
    for (int ks = 0; ks < 8; ks++) {
        uint32_t af[2][4];
        #pragma unroll
        for (int mi = 0; mi < 2; mi++) {
            int row = wm * 32 + mi * 16 + (lane & 15);
            int ql  = ks * 2 + (lane >> 4);
            ldsm4(af[mi], sb + SMEM_A + row * 256 + ((ql ^ (row & 7)) * 16));
        }
        uint32_t bfm[4][4];
        #pragma unroll
        for (int bi = 0; bi < 4; bi++) {
            int row = wn * 64 + bi * 16 + (lane & 15);
            int ql  = ks * 2 + (lane >> 4);
            ldsm4(bfm[bi], sb + SMEM_B + row * 256 + ((ql ^ (row & 7)) * 16));
        }
        #pragma unroll
        for (int mi = 0; mi < 2; mi++)
            #pragma unroll
            for (int bi = 0; bi < 4; bi++) {
                mma16816(acc[mi][bi * 2 + 0], af[mi], bfm[bi][0], bfm[bi][2]);
                mma16816(acc[mi][bi * 2 + 1], af[mi], bfm[bi][1], bfm[bi][3]);
            }
    }

    // ---- epilogue: row max always; exp only if exponent > -75 (never) ----
    int grow[4]; float d4[4]; int rl[4]; float mx4[4], ac4[4];
    #pragma unroll
    for (int s = 0; s < 4; s++) {
        int mi = s >> 1, h = s & 1;
        grow[s] = rowbase + wm * 32 + mi * 16 + h * 8 + (lane >> 2);
        d4[s]   = dG[grow[s]];
        rl[s]   = labG[grow[s]];
        mx4[s]  = -1e30f;
        ac4[s]  = 0.f;
    }
    const int* labC = reinterpret_cast<const int*>(smem + SMEM_LAB);
    #pragma unroll
    for (int mi = 0; mi < 2; mi++)
        #pragma unroll
        for (int bi = 0; bi < 8; bi++)
            #pragma unroll
            for (int rg = 0; rg < 4; rg++) {
                int s = mi * 2 + (rg >> 1);
                float sim = acc[mi][bi][rg] * INVT;
                mx4[s] = fmaxf(mx4[s], sim);
                float tt = sim - d4[s];
                if (__builtin_expect(tt > -75.f, 0)) {
                    int cl   = wn * 64 + bi * 8 + (lane & 3) * 2 + (rg & 1);
                    int gcol = colbase + cl;
                    if (gcol != grow[s]) {
                        float e = __expf(tt);
                        ac4[s] += (rl[s] == labC[cl]) ? e : -e;
                    }
                }
            }
    #pragma unroll
    for (int s = 0; s < 4; s++) {
        float a = ac4[s], m = mx4[s];
        a += __shfl_xor_sync(0xffffffffu, a, 1);
        a += __shfl_xor_sync(0xffffffffu, a, 2);
        m = fmaxf(m, __shfl_xor_sync(0xffffffffu, m, 1));
        m = fmaxf(m, __shfl_xor_sync(0xffffffffu, m, 2));
        if ((lane & 3) == 0) {
            atomicAdd(&accG[grow[s]], a);
            atomicMax(&mG[grow[s]], fenc(m));
        }
    }
}

// ---- kernel 3: exact max rebase + mean -----------------------------------
__global__ void final_kernel(float* __restrict__ out) {
    __shared__ double red[1024];
    int t = threadIdx.x;
    double s = 0.0;
    #pragma unroll
    for (int i = 0; i < 8; i++) {
        int r = t + i * 1024;
        float m = fdec(mG[r]);
        s += (double)(accG[r] * __expf(dG[r] - m));
    }
    red[t] = s;
    __syncthreads();
    for (int o = 512; o; o >>= 1) {
        if (t < o) red[t] += red[t + o];
        __syncthreads();
    }
    if (t == 0) out[0] = (float)(-red[0] / (double)M_TOTAL);
}

// ---- host ----------------------------------------------------------------
extern "C" void kernel_launch(void* const* d_in, const int* in_sizes, int n_in,
                              void* d_out, int out_size) {
    const float*     feat   = (const float*)d_in[0];
    const long long* labels = (const long long*)d_in[1];
    float* out = (float*)d_out;

    cudaFuncSetAttribute(main_kernel, cudaFuncAttributeMaxDynamicSharedMemorySize, SMEM_SZ);

    prep_kernel<<<M_TOTAL / 8, 256>>>(feat, labels);
    main_kernel<<<dim3(64, 64), 256, SMEM_SZ>>>();
    final_kernel<<<1, 1024>>>(out);
}